// round 5
// baseline (speedup 1.0000x reference)
#include <cuda_runtime.h>
#include <cstdint>

#define NN 50000
#define EE 800000
#define DD 128
#define NB 49   // scan blocks: ceil(50000/1024)

// ---- device scratch (no allocs allowed) ----
__device__ float g_agg[NN * DD];
__device__ float g_h1[NN * DD];
__device__ float g_h2[NN * DD];
__device__ int   g_cnt[NN];
__device__ int   g_pos[NN];
__device__ int   g_row[NN + 1];
__device__ float g_inv[NN];
__device__ int   g_srcl[EE];
__device__ int   g_is64;
__device__ int   g_bsum[64];
__device__ int   g_boff[64];

// ---- packed f32x2 helpers (Blackwell base-target: sm_100+) ----
#define FMA2(d, a, b) \
    asm("fma.rn.f32x2 %0, %1, %2, %0;" : "+l"(d) : "l"(a), "l"(b))
#define PACK2(out, lo, hi) \
    asm("mov.b64 %0, {%1, %2};" : "=l"(out) : "f"(lo), "f"(hi))
#define UNPACK2(lo, hi, in) \
    asm("mov.b64 {%0, %1}, %2;" : "=f"(lo), "=f"(hi) : "l"(in))

// ---------------- edge dtype detection (warp-parallel) ----------------
// JAX x64-disabled canonicalizes int64 -> int32. For little-endian int64
// values in [0, 50000) every odd 32-bit word is 0.
__global__ void k_detect(const int* __restrict__ eiw) {
    int t = threadIdx.x;
    int bad = 0;
    for (int i = 2 * t + 1; i < 4096; i += 64)
        if (eiw[i] != 0) bad = 1;
    unsigned m = __ballot_sync(0xffffffffu, bad);
    if (t == 0) g_is64 = (m == 0);
}
__device__ __forceinline__ int edge_at(const int* __restrict__ eiw, int idx) {
    return g_is64 ? eiw[2 * idx] : eiw[idx];
}

// ---------------- CSR build ----------------
__global__ void k_zero_cnt() {
    int i = blockIdx.x * blockDim.x + threadIdx.x;
    if (i < NN) g_cnt[i] = 0;
}
__global__ void k_count(const int* __restrict__ eiw) {
    int e = blockIdx.x * blockDim.x + threadIdx.x;
    if (e < EE) atomicAdd(&g_cnt[edge_at(eiw, EE + e)], 1);
}
__global__ void __launch_bounds__(1024) k_scan1() {
    int b = blockIdx.x, t = threadIdx.x;
    int i = b * 1024 + t;
    int v = (i < NN) ? g_cnt[i] : 0;
    int lane = t & 31, w = t >> 5;
    int x = v;
#pragma unroll
    for (int o = 1; o < 32; o <<= 1) {
        int y = __shfl_up_sync(0xffffffffu, x, o);
        if (lane >= o) x += y;
    }
    __shared__ int ws[32];
    if (lane == 31) ws[w] = x;
    __syncthreads();
    if (w == 0) {
        int y = ws[lane];
#pragma unroll
        for (int o = 1; o < 32; o <<= 1) {
            int z = __shfl_up_sync(0xffffffffu, y, o);
            if (lane >= o) y += z;
        }
        ws[lane] = y;
    }
    __syncthreads();
    int incl = x + (w > 0 ? ws[w - 1] : 0);
    if (i < NN) g_row[i] = incl - v;
    if (t == 1023) g_bsum[b] = incl;
}
__global__ void k_scan2() {
    int lane = threadIdx.x;
    int v0 = (lane < NB) ? g_bsum[lane] : 0;
    int v1 = (32 + lane < NB) ? g_bsum[32 + lane] : 0;
    int x0 = v0, x1 = v1;
#pragma unroll
    for (int o = 1; o < 32; o <<= 1) {
        int y = __shfl_up_sync(0xffffffffu, x0, o);
        if (lane >= o) x0 += y;
    }
    int tot0 = __shfl_sync(0xffffffffu, x0, 31);
#pragma unroll
    for (int o = 1; o < 32; o <<= 1) {
        int y = __shfl_up_sync(0xffffffffu, x1, o);
        if (lane >= o) x1 += y;
    }
    if (lane < NB) g_boff[lane] = x0 - v0;
    if (32 + lane < NB) g_boff[32 + lane] = tot0 + x1 - v1;
    if (lane == 31) g_row[NN] = tot0 + __shfl_sync(0xffffffffu, x1, 31);
}
__global__ void __launch_bounds__(1024) k_scan3() {
    int i = blockIdx.x * 1024 + threadIdx.x;
    if (i < NN) {
        int r = g_row[i] + g_boff[blockIdx.x];
        g_row[i] = r;
        g_pos[i] = r;
        int c = g_cnt[i];
        g_inv[i] = 1.0f / (float)(c > 0 ? c : 1);
    }
}
__global__ void k_fill(const int* __restrict__ eiw) {
    int e = blockIdx.x * blockDim.x + threadIdx.x;
    if (e < EE) {
        int d = edge_at(eiw, EE + e);
        int p = atomicAdd(&g_pos[d], 1);
        g_srcl[p] = edge_at(eiw, e);
    }
}

// ---------------- mean aggregation: one warp per node ----------------
__global__ void k_aggregate(const float* __restrict__ hext, int sel) {
    const float* h = (sel == 1) ? (const float*)g_h1
                   : (sel == 2) ? (const float*)g_h2 : hext;
    int w = (blockIdx.x * blockDim.x + threadIdx.x) >> 5;
    int lane = threadIdx.x & 31;
    if (w >= NN) return;
    int s = g_row[w], e = g_row[w + 1];
    float4 acc = make_float4(0.f, 0.f, 0.f, 0.f);
    for (int i = s; i < e; ++i) {
        int src = g_srcl[i];
        float4 v = *(const float4*)(h + (size_t)src * DD + lane * 4);
        acc.x += v.x; acc.y += v.y; acc.z += v.z; acc.w += v.w;
    }
    float iv = g_inv[w];
    float4 r = make_float4(acc.x * iv, acc.y * iv, acc.z * iv, acc.w * iv);
    *(float4*)(g_agg + (size_t)w * DD + lane * 4) = r;
}

// ---------------- fused SAGE GEMM (packed f32x2 FMA) ----------------
// out[n][o] = relu?( agg[n,:]·Wl[o,:] + Aself[n,:]·Wr[o,:] + b[o] )
// 128-node x 128-out tile, 256 threads, 8x8 micro-tile with accumulators
// packed pairwise along rows (FFMA2 doubles fp32 MACs per issue).
__global__ void __launch_bounds__(256) k_gemm(
    const float* __restrict__ aself_ext, int asel,
    const float* __restrict__ Wl, const float* __restrict__ Wr,
    const float* __restrict__ bias,
    float* out_ext, int osel, int do_relu)
{
    const float* Aself = (asel == 1) ? (const float*)g_h1
                       : (asel == 2) ? (const float*)g_h2 : aself_ext;
    float* out = (osel == 1) ? (float*)g_h1
               : (osel == 2) ? (float*)g_h2 : out_ext;

    __shared__ float AsT[16 * 128];                     // AsT[kk][r]
    __shared__ unsigned long long Ws2[16 * 128];        // Ws2[kk][o] = (w,w)

    int t = threadIdx.x;
    int n0 = blockIdx.x * 128;
    int tr = t >> 4, tc = t & 15;
    int r0 = tr * 8, c0 = tc * 8;

    unsigned long long acc[4][8];   // acc[i2][j]: rows (r0+2i2, r0+2i2+1), col c0+j
    {
        unsigned long long z; PACK2(z, 0.f, 0.f);
#pragma unroll
        for (int i = 0; i < 4; i++)
#pragma unroll
            for (int j = 0; j < 8; j++) acc[i][j] = z;
    }

#pragma unroll 1
    for (int phase = 0; phase < 2; ++phase) {
        const float* A = phase ? Aself : (const float*)g_agg;
        const float* W = phase ? Wr : Wl;
        const float4* A4 = (const float4*)A;
        const float4* W4 = (const float4*)W;
#pragma unroll 1
        for (int k0 = 0; k0 < 128; k0 += 16) {
            // A tile: 128 rows x 16 k, transposed into AsT[kk][r]
#pragma unroll
            for (int rep = 0; rep < 2; ++rep) {
                int idx = rep * 256 + t;       // 0..511
                int r = idx >> 2, q = idx & 3;
                int n = n0 + r;
                float4 v = make_float4(0.f, 0.f, 0.f, 0.f);
                if (n < NN) v = A4[(size_t)n * 32 + (k0 >> 2) + q];
                int kk = q * 4;
                AsT[(kk + 0) * 128 + r] = v.x;
                AsT[(kk + 1) * 128 + r] = v.y;
                AsT[(kk + 2) * 128 + r] = v.z;
                AsT[(kk + 3) * 128 + r] = v.w;
            }
            // W tile transposed + duplicated: Ws2[kk][o] = (W[o][k0+kk], same)
#pragma unroll
            for (int rep = 0; rep < 2; ++rep) {
                int idx = rep * 256 + t;
                int o = idx >> 2, q = idx & 3;
                float4 v = W4[o * 32 + (k0 >> 2) + q];
                int kk = q * 4;
                unsigned long long d0, d1, d2, d3;
                PACK2(d0, v.x, v.x); PACK2(d1, v.y, v.y);
                PACK2(d2, v.z, v.z); PACK2(d3, v.w, v.w);
                Ws2[(kk + 0) * 128 + o] = d0;
                Ws2[(kk + 1) * 128 + o] = d1;
                Ws2[(kk + 2) * 128 + o] = d2;
                Ws2[(kk + 3) * 128 + o] = d3;
            }
            __syncthreads();
#pragma unroll
            for (int kk = 0; kk < 16; ++kk) {
                // a-pairs: rows (r0..r0+7) as 4 packed u64, 2x LDS.128
                ulonglong2 a01 = *(const ulonglong2*)&AsT[kk * 128 + r0];
                ulonglong2 a23 = *(const ulonglong2*)&AsT[kk * 128 + r0 + 4];
                // w-dups: 8 packed u64, 4x LDS.128
                ulonglong2 w01 = *(const ulonglong2*)&Ws2[kk * 128 + c0];
                ulonglong2 w23 = *(const ulonglong2*)&Ws2[kk * 128 + c0 + 2];
                ulonglong2 w45 = *(const ulonglong2*)&Ws2[kk * 128 + c0 + 4];
                ulonglong2 w67 = *(const ulonglong2*)&Ws2[kk * 128 + c0 + 6];
                unsigned long long av[4] = { a01.x, a01.y, a23.x, a23.y };
                unsigned long long wv[8] = { w01.x, w01.y, w23.x, w23.y,
                                             w45.x, w45.y, w67.x, w67.y };
#pragma unroll
                for (int i = 0; i < 4; i++)
#pragma unroll
                    for (int j = 0; j < 8; j++)
                        FMA2(acc[i][j], av[i], wv[j]);
            }
            __syncthreads();
        }
    }

    float bv[8];
#pragma unroll
    for (int j = 0; j < 8; j++) bv[j] = bias[c0 + j];

#pragma unroll
    for (int i = 0; i < 4; i++) {
        float lo[8], hi[8];
#pragma unroll
        for (int j = 0; j < 8; j++) {
            UNPACK2(lo[j], hi[j], acc[i][j]);
            lo[j] += bv[j]; hi[j] += bv[j];
            if (do_relu) { lo[j] = fmaxf(lo[j], 0.f); hi[j] = fmaxf(hi[j], 0.f); }
        }
        int ne = n0 + r0 + 2 * i;
        if (ne < NN) {
            *(float4*)(out + (size_t)ne * DD + c0) =
                make_float4(lo[0], lo[1], lo[2], lo[3]);
            *(float4*)(out + (size_t)ne * DD + c0 + 4) =
                make_float4(lo[4], lo[5], lo[6], lo[7]);
        }
        if (ne + 1 < NN) {
            *(float4*)(out + (size_t)(ne + 1) * DD + c0) =
                make_float4(hi[0], hi[1], hi[2], hi[3]);
            *(float4*)(out + (size_t)(ne + 1) * DD + c0 + 4) =
                make_float4(hi[4], hi[5], hi[6], hi[7]);
        }
    }
}

// ---------------- decoder: one warp per node ----------------
__global__ void k_decoder(const float* __restrict__ h3, const float* __restrict__ Wo,
                          const float* __restrict__ bo, float* __restrict__ out2) {
    int w = (blockIdx.x * blockDim.x + threadIdx.x) >> 5;
    int lane = threadIdx.x & 31;
    if (w >= NN) return;
    float4 h  = *(const float4*)(h3 + (size_t)w * DD + lane * 4);
    float4 w0 = *(const float4*)(Wo + lane * 4);
    float4 w1 = *(const float4*)(Wo + DD + lane * 4);
    float p0 = h.x * w0.x + h.y * w0.y + h.z * w0.z + h.w * w0.w;
    float p1 = h.x * w1.x + h.y * w1.y + h.z * w1.z + h.w * w1.w;
    for (int off = 16; off; off >>= 1) {
        p0 += __shfl_xor_sync(0xffffffffu, p0, off);
        p1 += __shfl_xor_sync(0xffffffffu, p1, off);
    }
    if (lane == 0) {
        out2[w * 2 + 0] = p0 + bo[0];
        out2[w * 2 + 1] = p1 + bo[1];
    }
}

extern "C" void kernel_launch(void* const* d_in, const int* in_sizes, int n_in,
                              void* d_out, int out_size) {
    const float* x   = (const float*)d_in[0];
    const int*   eiw = (const int*)d_in[1];
    const float* Wl1 = (const float*)d_in[2];
    const float* Wr1 = (const float*)d_in[3];
    const float* b1  = (const float*)d_in[4];
    const float* Wl2 = (const float*)d_in[5];
    const float* Wr2 = (const float*)d_in[6];
    const float* b2  = (const float*)d_in[7];
    const float* Wl3 = (const float*)d_in[8];
    const float* Wr3 = (const float*)d_in[9];
    const float* b3  = (const float*)d_in[10];
    const float* Wo  = (const float*)d_in[11];
    const float* bo  = (const float*)d_in[12];

    float* out  = (float*)d_out;
    float* out2 = out;              // [N, 2]
    float* h3   = out + NN * 2;     // [N, 128]

    // CSR build (edges identical across layers)
    k_detect<<<1, 32>>>(eiw);
    k_zero_cnt<<<(NN + 255) / 256, 256>>>();
    k_count<<<(EE + 255) / 256, 256>>>(eiw);
    k_scan1<<<NB, 1024>>>();
    k_scan2<<<1, 32>>>();
    k_scan3<<<NB, 1024>>>();
    k_fill<<<(EE + 255) / 256, 256>>>(eiw);

    int gemm_blocks = (NN + 127) / 128;
    int warp_blocks = (NN + 7) / 8;

    // layer 1: x -> g_h1 (relu)
    k_aggregate<<<warp_blocks, 256>>>(x, 0);
    k_gemm<<<gemm_blocks, 256>>>(x, 0, Wl1, Wr1, b1, nullptr, 1, 1);

    // layer 2: g_h1 -> g_h2 (relu)
    k_aggregate<<<warp_blocks, 256>>>(nullptr, 1);
    k_gemm<<<gemm_blocks, 256>>>(nullptr, 1, Wl2, Wr2, b2, nullptr, 2, 1);

    // layer 3: g_h2 -> h3 (no relu), straight into d_out
    k_aggregate<<<warp_blocks, 256>>>(nullptr, 2);
    k_gemm<<<gemm_blocks, 256>>>(nullptr, 2, Wl3, Wr3, b3, h3, 0, 0);

    // decoder
    k_decoder<<<warp_blocks, 256>>>(h3, Wo, bo, out2);
}

// round 6
// speedup vs baseline: 1.6394x; 1.6394x over previous
#include <cuda_runtime.h>
#include <cstdint>

#define NN 50000
#define EE 800000
#define DD 128
#define NB 49                 // scan blocks: ceil(50000/1024)
#define GB 391                // gemm blocks: ceil(50000/128)
#define AGGB 6250             // aggregate blocks: ceil(50000/8)

// ---- device scratch (no allocs allowed) ----
__device__ float g_agg[NN * DD];
__device__ float g_s[NN * DD];     // self-term S = h·Wr^T + b
__device__ float g_h1[NN * DD];
__device__ float g_h2[NN * DD];
__device__ int   g_cnt[NN];
__device__ int   g_pos[NN];
__device__ int   g_row[NN + 1];
__device__ float g_inv[NN];
__device__ int   g_srcl[EE];
__device__ int   g_is64;
__device__ int   g_bsum[64];
__device__ int   g_boff[64];

// ---------------- edge dtype detection (warp-parallel) ----------------
// JAX x64-disabled canonicalizes int64 -> int32. For little-endian int64
// values in [0, 50000) every odd 32-bit word is 0.
__global__ void k_detect(const int* __restrict__ eiw) {
    int t = threadIdx.x;
    int bad = 0;
    for (int i = 2 * t + 1; i < 4096; i += 64)
        if (eiw[i] != 0) bad = 1;
    unsigned m = __ballot_sync(0xffffffffu, bad);
    if (t == 0) g_is64 = (m == 0);
}
__device__ __forceinline__ int edge_at(const int* __restrict__ eiw, int idx) {
    return g_is64 ? eiw[2 * idx] : eiw[idx];
}

// ---------------- CSR build ----------------
__global__ void k_zero_cnt() {
    int i = blockIdx.x * blockDim.x + threadIdx.x;
    if (i < NN) g_cnt[i] = 0;
}
__global__ void k_count(const int* __restrict__ eiw) {
    int e = blockIdx.x * blockDim.x + threadIdx.x;
    if (e < EE) atomicAdd(&g_cnt[edge_at(eiw, EE + e)], 1);
}
__global__ void __launch_bounds__(1024) k_scan1() {
    int b = blockIdx.x, t = threadIdx.x;
    int i = b * 1024 + t;
    int v = (i < NN) ? g_cnt[i] : 0;
    int lane = t & 31, w = t >> 5;
    int x = v;
#pragma unroll
    for (int o = 1; o < 32; o <<= 1) {
        int y = __shfl_up_sync(0xffffffffu, x, o);
        if (lane >= o) x += y;
    }
    __shared__ int ws[32];
    if (lane == 31) ws[w] = x;
    __syncthreads();
    if (w == 0) {
        int y = ws[lane];
#pragma unroll
        for (int o = 1; o < 32; o <<= 1) {
            int z = __shfl_up_sync(0xffffffffu, y, o);
            if (lane >= o) y += z;
        }
        ws[lane] = y;
    }
    __syncthreads();
    int incl = x + (w > 0 ? ws[w - 1] : 0);
    if (i < NN) g_row[i] = incl - v;
    if (t == 1023) g_bsum[b] = incl;
}
__global__ void k_scan2() {
    int lane = threadIdx.x;
    int v0 = (lane < NB) ? g_bsum[lane] : 0;
    int v1 = (32 + lane < NB) ? g_bsum[32 + lane] : 0;
    int x0 = v0, x1 = v1;
#pragma unroll
    for (int o = 1; o < 32; o <<= 1) {
        int y = __shfl_up_sync(0xffffffffu, x0, o);
        if (lane >= o) x0 += y;
    }
    int tot0 = __shfl_sync(0xffffffffu, x0, 31);
#pragma unroll
    for (int o = 1; o < 32; o <<= 1) {
        int y = __shfl_up_sync(0xffffffffu, x1, o);
        if (lane >= o) x1 += y;
    }
    if (lane < NB) g_boff[lane] = x0 - v0;
    if (32 + lane < NB) g_boff[32 + lane] = tot0 + x1 - v1;
    if (lane == 31) g_row[NN] = tot0 + __shfl_sync(0xffffffffu, x1, 31);
}
__global__ void __launch_bounds__(1024) k_scan3() {
    int i = blockIdx.x * 1024 + threadIdx.x;
    if (i < NN) {
        int r = g_row[i] + g_boff[blockIdx.x];
        g_row[i] = r;
        g_pos[i] = r;
        int c = g_cnt[i];
        g_inv[i] = 1.0f / (float)(c > 0 ? c : 1);
    }
}
__global__ void k_fill(const int* __restrict__ eiw) {
    int e = blockIdx.x * blockDim.x + threadIdx.x;
    if (e < EE) {
        int d = edge_at(eiw, EE + e);
        int p = atomicAdd(&g_pos[d], 1);
        g_srcl[p] = edge_at(eiw, e);
    }
}

// ================= layer building blocks =================

// GEMM tile core: acc += A_tile(128 rows from n0) x W^T over K=128.
// 256 threads, 8x8 micro-tile, K tiled by 16. Caller owns epilogue.
__device__ __forceinline__ void gemm_core(
    const float* __restrict__ A, const float* __restrict__ W,
    int n0, int t, float* AsT, float* Ws, float acc[8][8])
{
    int tr = t >> 4, tc = t & 15;
    int r0 = tr * 8, c0 = tc * 8;
    const float4* A4 = (const float4*)A;
    const float4* W4 = (const float4*)W;
#pragma unroll 1
    for (int k0 = 0; k0 < 128; k0 += 16) {
        // A tile: 128 rows x 16 k, transposed into AsT[kk][r]
#pragma unroll
        for (int rep = 0; rep < 2; ++rep) {
            int idx = rep * 256 + t;       // 0..511
            int r = idx >> 2, q = idx & 3;
            int n = n0 + r;
            float4 v = make_float4(0.f, 0.f, 0.f, 0.f);
            if (n < NN) v = A4[(size_t)n * 32 + (k0 >> 2) + q];
            int kk = q * 4;
            AsT[(kk + 0) * 128 + r] = v.x;
            AsT[(kk + 1) * 128 + r] = v.y;
            AsT[(kk + 2) * 128 + r] = v.z;
            AsT[(kk + 3) * 128 + r] = v.w;
        }
        // W tile transposed: Ws[kk][o] = W[o][k0+kk]
#pragma unroll
        for (int rep = 0; rep < 2; ++rep) {
            int idx = rep * 256 + t;
            int o = idx >> 2, q = idx & 3;
            float4 v = W4[o * 32 + (k0 >> 2) + q];
            int kk = q * 4;
            Ws[(kk + 0) * 128 + o] = v.x;
            Ws[(kk + 1) * 128 + o] = v.y;
            Ws[(kk + 2) * 128 + o] = v.z;
            Ws[(kk + 3) * 128 + o] = v.w;
        }
        __syncthreads();
#pragma unroll
        for (int kk = 0; kk < 16; ++kk) {
            float4 a0 = *(float4*)&AsT[kk * 128 + r0];
            float4 a1 = *(float4*)&AsT[kk * 128 + r0 + 4];
            float4 w0 = *(float4*)&Ws[kk * 128 + c0];
            float4 w1 = *(float4*)&Ws[kk * 128 + c0 + 4];
            float av[8] = { a0.x, a0.y, a0.z, a0.w, a1.x, a1.y, a1.z, a1.w };
            float wv[8] = { w0.x, w0.y, w0.z, w0.w, w1.x, w1.y, w1.z, w1.w };
#pragma unroll
            for (int i = 0; i < 8; i++)
#pragma unroll
                for (int j = 0; j < 8; j++)
                    acc[i][j] += av[i] * wv[j];
        }
        __syncthreads();
    }
}

// mega kernel: blocks [0, GB) compute S = h·Wr^T + b (FMA-bound);
// blocks [GB, GB+AGGB) do mean-aggregation of h into g_agg (L2-bound).
// The two populations touch disjoint pipes and run concurrently.
__global__ void __launch_bounds__(256) k_mega(
    const float* __restrict__ hext, int sel,
    const float* __restrict__ Wr, const float* __restrict__ bias)
{
    const float* h = (sel == 1) ? (const float*)g_h1
                   : (sel == 2) ? (const float*)g_h2 : hext;
    __shared__ float AsT[16 * 128];
    __shared__ float Ws[16 * 128];

    if (blockIdx.x < GB) {
        // ---- self GEMM: g_s = h·Wr^T + bias ----
        int t = threadIdx.x;
        int n0 = blockIdx.x * 128;
        int tr = t >> 4, tc = t & 15;
        int r0 = tr * 8, c0 = tc * 8;
        float acc[8][8];
#pragma unroll
        for (int i = 0; i < 8; i++)
#pragma unroll
            for (int j = 0; j < 8; j++) acc[i][j] = 0.f;
        gemm_core(h, Wr, n0, t, AsT, Ws, acc);
        float bv[8];
#pragma unroll
        for (int j = 0; j < 8; j++) bv[j] = bias[c0 + j];
#pragma unroll
        for (int i = 0; i < 8; i++) {
            int n = n0 + r0 + i;
            if (n < NN) {
                *(float4*)(g_s + (size_t)n * DD + c0) =
                    make_float4(acc[i][0] + bv[0], acc[i][1] + bv[1],
                                acc[i][2] + bv[2], acc[i][3] + bv[3]);
                *(float4*)(g_s + (size_t)n * DD + c0 + 4) =
                    make_float4(acc[i][4] + bv[4], acc[i][5] + bv[5],
                                acc[i][6] + bv[6], acc[i][7] + bv[7]);
            }
        }
    } else {
        // ---- mean aggregation: one warp per node ----
        int bid = blockIdx.x - GB;
        int w = bid * 8 + (threadIdx.x >> 5);
        int lane = threadIdx.x & 31;
        if (w >= NN) return;
        int s = g_row[w], e = g_row[w + 1];
        float4 acc = make_float4(0.f, 0.f, 0.f, 0.f);
        for (int i = s; i < e; ++i) {
            int src = g_srcl[i];
            float4 v = *(const float4*)(h + (size_t)src * DD + lane * 4);
            acc.x += v.x; acc.y += v.y; acc.z += v.z; acc.w += v.w;
        }
        float iv = g_inv[w];
        *(float4*)(g_agg + (size_t)w * DD + lane * 4) =
            make_float4(acc.x * iv, acc.y * iv, acc.z * iv, acc.w * iv);
    }
}

// agg GEMM: out = relu?( g_agg·Wl^T + g_s )
__global__ void __launch_bounds__(256) k_gemm_agg(
    const float* __restrict__ Wl, float* out_ext, int osel, int do_relu)
{
    float* out = (osel == 1) ? (float*)g_h1
               : (osel == 2) ? (float*)g_h2 : out_ext;
    __shared__ float AsT[16 * 128];
    __shared__ float Ws[16 * 128];

    int t = threadIdx.x;
    int n0 = blockIdx.x * 128;
    int tr = t >> 4, tc = t & 15;
    int r0 = tr * 8, c0 = tc * 8;
    float acc[8][8];
#pragma unroll
    for (int i = 0; i < 8; i++)
#pragma unroll
        for (int j = 0; j < 8; j++) acc[i][j] = 0.f;
    gemm_core((const float*)g_agg, Wl, n0, t, AsT, Ws, acc);

#pragma unroll
    for (int i = 0; i < 8; i++) {
        int n = n0 + r0 + i;
        if (n < NN) {
            float4 s0 = *(const float4*)(g_s + (size_t)n * DD + c0);
            float4 s1 = *(const float4*)(g_s + (size_t)n * DD + c0 + 4);
            float v0 = acc[i][0] + s0.x, v1 = acc[i][1] + s0.y;
            float v2 = acc[i][2] + s0.z, v3 = acc[i][3] + s0.w;
            float v4 = acc[i][4] + s1.x, v5 = acc[i][5] + s1.y;
            float v6 = acc[i][6] + s1.z, v7 = acc[i][7] + s1.w;
            if (do_relu) {
                v0 = fmaxf(v0, 0.f); v1 = fmaxf(v1, 0.f);
                v2 = fmaxf(v2, 0.f); v3 = fmaxf(v3, 0.f);
                v4 = fmaxf(v4, 0.f); v5 = fmaxf(v5, 0.f);
                v6 = fmaxf(v6, 0.f); v7 = fmaxf(v7, 0.f);
            }
            *(float4*)(out + (size_t)n * DD + c0)     = make_float4(v0, v1, v2, v3);
            *(float4*)(out + (size_t)n * DD + c0 + 4) = make_float4(v4, v5, v6, v7);
        }
    }
}

// ---------------- decoder: one warp per node ----------------
__global__ void k_decoder(const float* __restrict__ h3, const float* __restrict__ Wo,
                          const float* __restrict__ bo, float* __restrict__ out2) {
    int w = (blockIdx.x * blockDim.x + threadIdx.x) >> 5;
    int lane = threadIdx.x & 31;
    if (w >= NN) return;
    float4 h  = *(const float4*)(h3 + (size_t)w * DD + lane * 4);
    float4 w0 = *(const float4*)(Wo + lane * 4);
    float4 w1 = *(const float4*)(Wo + DD + lane * 4);
    float p0 = h.x * w0.x + h.y * w0.y + h.z * w0.z + h.w * w0.w;
    float p1 = h.x * w1.x + h.y * w1.y + h.z * w1.z + h.w * w1.w;
    for (int off = 16; off; off >>= 1) {
        p0 += __shfl_xor_sync(0xffffffffu, p0, off);
        p1 += __shfl_xor_sync(0xffffffffu, p1, off);
    }
    if (lane == 0) {
        out2[w * 2 + 0] = p0 + bo[0];
        out2[w * 2 + 1] = p1 + bo[1];
    }
}

extern "C" void kernel_launch(void* const* d_in, const int* in_sizes, int n_in,
                              void* d_out, int out_size) {
    const float* x   = (const float*)d_in[0];
    const int*   eiw = (const int*)d_in[1];
    const float* Wl1 = (const float*)d_in[2];
    const float* Wr1 = (const float*)d_in[3];
    const float* b1  = (const float*)d_in[4];
    const float* Wl2 = (const float*)d_in[5];
    const float* Wr2 = (const float*)d_in[6];
    const float* b2  = (const float*)d_in[7];
    const float* Wl3 = (const float*)d_in[8];
    const float* Wr3 = (const float*)d_in[9];
    const float* b3  = (const float*)d_in[10];
    const float* Wo  = (const float*)d_in[11];
    const float* bo  = (const float*)d_in[12];

    float* out  = (float*)d_out;
    float* out2 = out;              // [N, 2]
    float* h3   = out + NN * 2;     // [N, 128]

    // CSR build (edges identical across layers)
    k_detect<<<1, 32>>>(eiw);
    k_zero_cnt<<<(NN + 255) / 256, 256>>>();
    k_count<<<(EE + 255) / 256, 256>>>(eiw);
    k_scan1<<<NB, 1024>>>();
    k_scan2<<<1, 32>>>();
    k_scan3<<<NB, 1024>>>();
    k_fill<<<(EE + 255) / 256, 256>>>(eiw);

    const int mega_blocks = GB + AGGB;

    // layer 1: x -> g_h1 (relu)
    k_mega<<<mega_blocks, 256>>>(x, 0, Wr1, b1);
    k_gemm_agg<<<GB, 256>>>(Wl1, nullptr, 1, 1);

    // layer 2: g_h1 -> g_h2 (relu)
    k_mega<<<mega_blocks, 256>>>(nullptr, 1, Wr2, b2);
    k_gemm_agg<<<GB, 256>>>(Wl2, nullptr, 2, 1);

    // layer 3: g_h2 -> h3 (no relu), straight into d_out
    k_mega<<<mega_blocks, 256>>>(nullptr, 2, Wr3, b3);
    k_gemm_agg<<<GB, 256>>>(Wl3, h3, 0, 0);

    // decoder
    k_decoder<<<(NN + 7) / 8, 256>>>(h3, Wo, bo, out2);
}

// round 7
// speedup vs baseline: 2.8529x; 1.7402x over previous
#include <cuda_runtime.h>
#include <cuda_bf16.h>
#include <cstdint>

#define NN 50000
#define EE 800000
#define DD 128
#define NB 49                 // scan blocks: ceil(50000/1024)
#define GB 391                // gemm blocks: ceil(50000/128)

// ---- device scratch (no allocs allowed) ----
__device__ float g_agg[NN * DD];
__device__ float g_h1[NN * DD];
__device__ float g_h2[NN * DD];
__device__ int   g_cnt[NN];
__device__ int   g_pos[NN];
__device__ int   g_row[NN + 1];
__device__ float g_inv[NN];
__device__ int   g_srcl[EE];
__device__ int   g_is64;
__device__ int   g_bsum[64];
__device__ int   g_boff[64];

// ---------------- edge dtype detection (warp-parallel) ----------------
__global__ void k_detect(const int* __restrict__ eiw) {
    int t = threadIdx.x;
    int bad = 0;
    for (int i = 2 * t + 1; i < 4096; i += 64)
        if (eiw[i] != 0) bad = 1;
    unsigned m = __ballot_sync(0xffffffffu, bad);
    if (t == 0) g_is64 = (m == 0);
}
__device__ __forceinline__ int edge_at(const int* __restrict__ eiw, int idx) {
    return g_is64 ? eiw[2 * idx] : eiw[idx];
}

// ---------------- CSR build ----------------
__global__ void k_zero_cnt() {
    int i = blockIdx.x * blockDim.x + threadIdx.x;
    if (i < NN) g_cnt[i] = 0;
}
__global__ void k_count(const int* __restrict__ eiw) {
    int e = blockIdx.x * blockDim.x + threadIdx.x;
    if (e < EE) atomicAdd(&g_cnt[edge_at(eiw, EE + e)], 1);
}
__global__ void __launch_bounds__(1024) k_scan1() {
    int b = blockIdx.x, t = threadIdx.x;
    int i = b * 1024 + t;
    int v = (i < NN) ? g_cnt[i] : 0;
    int lane = t & 31, w = t >> 5;
    int x = v;
#pragma unroll
    for (int o = 1; o < 32; o <<= 1) {
        int y = __shfl_up_sync(0xffffffffu, x, o);
        if (lane >= o) x += y;
    }
    __shared__ int ws[32];
    if (lane == 31) ws[w] = x;
    __syncthreads();
    if (w == 0) {
        int y = ws[lane];
#pragma unroll
        for (int o = 1; o < 32; o <<= 1) {
            int z = __shfl_up_sync(0xffffffffu, y, o);
            if (lane >= o) y += z;
        }
        ws[lane] = y;
    }
    __syncthreads();
    int incl = x + (w > 0 ? ws[w - 1] : 0);
    if (i < NN) g_row[i] = incl - v;
    if (t == 1023) g_bsum[b] = incl;
}
__global__ void k_scan2() {
    int lane = threadIdx.x;
    int v0 = (lane < NB) ? g_bsum[lane] : 0;
    int v1 = (32 + lane < NB) ? g_bsum[32 + lane] : 0;
    int x0 = v0, x1 = v1;
#pragma unroll
    for (int o = 1; o < 32; o <<= 1) {
        int y = __shfl_up_sync(0xffffffffu, x0, o);
        if (lane >= o) x0 += y;
    }
    int tot0 = __shfl_sync(0xffffffffu, x0, 31);
#pragma unroll
    for (int o = 1; o < 32; o <<= 1) {
        int y = __shfl_up_sync(0xffffffffu, x1, o);
        if (lane >= o) x1 += y;
    }
    if (lane < NB) g_boff[lane] = x0 - v0;
    if (32 + lane < NB) g_boff[32 + lane] = tot0 + x1 - v1;
    if (lane == 31) g_row[NN] = tot0 + __shfl_sync(0xffffffffu, x1, 31);
}
__global__ void __launch_bounds__(1024) k_scan3() {
    int i = blockIdx.x * 1024 + threadIdx.x;
    if (i < NN) {
        int r = g_row[i] + g_boff[blockIdx.x];
        g_row[i] = r;
        g_pos[i] = r;
        int c = g_cnt[i];
        g_inv[i] = 1.0f / (float)(c > 0 ? c : 1);
    }
}
__global__ void k_fill(const int* __restrict__ eiw) {
    int e = blockIdx.x * blockDim.x + threadIdx.x;
    if (e < EE) {
        int d = edge_at(eiw, EE + e);
        int p = atomicAdd(&g_pos[d], 1);
        g_srcl[p] = edge_at(eiw, e);
    }
}

// ---------------- mean aggregation: one warp per node ----------------
__global__ void k_aggregate(const float* __restrict__ hext, int sel) {
    const float* h = (sel == 1) ? (const float*)g_h1
                   : (sel == 2) ? (const float*)g_h2 : hext;
    int w = (blockIdx.x * blockDim.x + threadIdx.x) >> 5;
    int lane = threadIdx.x & 31;
    if (w >= NN) return;
    int s = g_row[w], e = g_row[w + 1];
    float4 acc = make_float4(0.f, 0.f, 0.f, 0.f);
    for (int i = s; i < e; ++i) {
        int src = g_srcl[i];
        float4 v = *(const float4*)(h + (size_t)src * DD + lane * 4);
        acc.x += v.x; acc.y += v.y; acc.z += v.z; acc.w += v.w;
    }
    float iv = g_inv[w];
    *(float4*)(g_agg + (size_t)w * DD + lane * 4) =
        make_float4(acc.x * iv, acc.y * iv, acc.z * iv, acc.w * iv);
}

// ================= HMMA bf16 3-product fused SAGE GEMM =================
// out[128xDD tile] = relu?( agg·Wl^T + h·Wr^T + b ), fp32 emulated via
// bf16 split: A·B ~= Ahi·Bhi + Alo·Bhi + Ahi·Blo (error ~2^-16).
// 256 threads = 8 warps; warp (mi, ni) owns 32x64 via m16n8k16 fragments.
// Smem tiles: [128 rows][32 k] bf16 pairs, row stride 20 u32 (conflict-free).

__device__ __forceinline__ void mma_bf16(float* d,
    uint32_t a0, uint32_t a1, uint32_t a2, uint32_t a3,
    uint32_t b0, uint32_t b1)
{
    asm volatile(
        "mma.sync.aligned.m16n8k16.row.col.f32.bf16.bf16.f32 "
        "{%0,%1,%2,%3}, {%4,%5,%6,%7}, {%8,%9}, {%0,%1,%2,%3};"
        : "+f"(d[0]), "+f"(d[1]), "+f"(d[2]), "+f"(d[3])
        : "r"(a0), "r"(a1), "r"(a2), "r"(a3), "r"(b0), "r"(b1));
}

__device__ __forceinline__ void split2(float x, float y, uint32_t& hi, uint32_t& lo) {
    __nv_bfloat16 hx = __float2bfloat16(x);
    __nv_bfloat16 hy = __float2bfloat16(y);
    __nv_bfloat16 lx = __float2bfloat16(x - __bfloat162float(hx));
    __nv_bfloat16 ly = __float2bfloat16(y - __bfloat162float(hy));
    hi = (uint32_t)__bfloat16_as_ushort(hx) | ((uint32_t)__bfloat16_as_ushort(hy) << 16);
    lo = (uint32_t)__bfloat16_as_ushort(lx) | ((uint32_t)__bfloat16_as_ushort(ly) << 16);
}

#define RS 20   // smem row stride in u32 (32 bf16 = 16 u32, +4 pad)

__global__ void __launch_bounds__(256) k_gemm(
    const float* __restrict__ aself_ext, int asel,
    const float* __restrict__ Wl, const float* __restrict__ Wr,
    const float* __restrict__ bias,
    float* out_ext, int osel, int do_relu)
{
    const float* Aself = (asel == 1) ? (const float*)g_h1
                       : (asel == 2) ? (const float*)g_h2 : aself_ext;
    float* out = (osel == 1) ? (float*)g_h1
               : (osel == 2) ? (float*)g_h2 : out_ext;

    __shared__ uint32_t sAhi[128 * RS], sAlo[128 * RS];
    __shared__ uint32_t sWhi[128 * RS], sWlo[128 * RS];

    int t = threadIdx.x;
    int lane = t & 31, w = t >> 5;
    int g = lane >> 2, tig = lane & 3;
    int mi = w & 3, ni = w >> 2;          // 4 m-warps x 2 n-warps
    int n0 = blockIdx.x * 128;

    float acc[2][8][4];
#pragma unroll
    for (int ms = 0; ms < 2; ++ms)
#pragma unroll
        for (int ns = 0; ns < 8; ++ns)
#pragma unroll
            for (int q = 0; q < 4; ++q) acc[ms][ns][q] = 0.f;

#pragma unroll 1
    for (int phase = 0; phase < 2; ++phase) {
        const float4* A4 = (const float4*)(phase ? Aself : (const float*)g_agg);
        const float4* W4 = (const float4*)(phase ? Wr : Wl);
#pragma unroll 1
        for (int kc = 0; kc < 4; ++kc) {
            // load + split A[128][32] and W[128][32] chunks
#pragma unroll
            for (int rep = 0; rep < 4; ++rep) {
                int idx = rep * 256 + t;      // 0..1023
                int r = idx >> 3, q = idx & 7;
                int n = n0 + r;
                float4 va = make_float4(0.f, 0.f, 0.f, 0.f);
                if (n < NN) va = A4[(size_t)n * 32 + kc * 8 + q];
                float4 vw = W4[r * 32 + kc * 8 + q];
                uint32_t h0, l0, h1, l1;
                int base = r * RS + q * 2;
                split2(va.x, va.y, h0, l0);
                split2(va.z, va.w, h1, l1);
                sAhi[base] = h0; sAhi[base + 1] = h1;
                sAlo[base] = l0; sAlo[base + 1] = l1;
                split2(vw.x, vw.y, h0, l0);
                split2(vw.z, vw.w, h1, l1);
                sWhi[base] = h0; sWhi[base + 1] = h1;
                sWlo[base] = l0; sWlo[base + 1] = l1;
            }
            __syncthreads();
#pragma unroll
            for (int ks = 0; ks < 2; ++ks) {
                int kof = ks * 8;             // u32 offset of this k-step
                uint32_t ahi[2][4], alo[2][4];
#pragma unroll
                for (int ms = 0; ms < 2; ++ms) {
                    int rb = (mi * 32 + ms * 16 + g) * RS + kof + tig;
                    int rb8 = rb + 8 * RS;
                    ahi[ms][0] = sAhi[rb];     ahi[ms][1] = sAhi[rb8];
                    ahi[ms][2] = sAhi[rb + 4]; ahi[ms][3] = sAhi[rb8 + 4];
                    alo[ms][0] = sAlo[rb];     alo[ms][1] = sAlo[rb8];
                    alo[ms][2] = sAlo[rb + 4]; alo[ms][3] = sAlo[rb8 + 4];
                }
#pragma unroll
                for (int ns = 0; ns < 8; ++ns) {
                    int ob = (ni * 64 + ns * 8 + g) * RS + kof + tig;
                    uint32_t bh0 = sWhi[ob], bh1 = sWhi[ob + 4];
                    uint32_t bl0 = sWlo[ob], bl1 = sWlo[ob + 4];
#pragma unroll
                    for (int ms = 0; ms < 2; ++ms) {
                        mma_bf16(acc[ms][ns], ahi[ms][0], ahi[ms][1], ahi[ms][2], ahi[ms][3], bh0, bh1);
                        mma_bf16(acc[ms][ns], alo[ms][0], alo[ms][1], alo[ms][2], alo[ms][3], bh0, bh1);
                        mma_bf16(acc[ms][ns], ahi[ms][0], ahi[ms][1], ahi[ms][2], ahi[ms][3], bl0, bl1);
                    }
                }
            }
            __syncthreads();
        }
    }

    // epilogue: bias + relu + store
#pragma unroll
    for (int ms = 0; ms < 2; ++ms) {
        int row0 = n0 + mi * 32 + ms * 16 + g;
        int row1 = row0 + 8;
#pragma unroll
        for (int ns = 0; ns < 8; ++ns) {
            int col = ni * 64 + ns * 8 + 2 * tig;
            float b0 = bias[col], b1 = bias[col + 1];
            float v00 = acc[ms][ns][0] + b0, v01 = acc[ms][ns][1] + b1;
            float v10 = acc[ms][ns][2] + b0, v11 = acc[ms][ns][3] + b1;
            if (do_relu) {
                v00 = fmaxf(v00, 0.f); v01 = fmaxf(v01, 0.f);
                v10 = fmaxf(v10, 0.f); v11 = fmaxf(v11, 0.f);
            }
            if (row0 < NN) *(float2*)(out + (size_t)row0 * DD + col) = make_float2(v00, v01);
            if (row1 < NN) *(float2*)(out + (size_t)row1 * DD + col) = make_float2(v10, v11);
        }
    }
}

// ---------------- decoder: one warp per node ----------------
__global__ void k_decoder(const float* __restrict__ h3, const float* __restrict__ Wo,
                          const float* __restrict__ bo, float* __restrict__ out2) {
    int w = (blockIdx.x * blockDim.x + threadIdx.x) >> 5;
    int lane = threadIdx.x & 31;
    if (w >= NN) return;
    float4 h  = *(const float4*)(h3 + (size_t)w * DD + lane * 4);
    float4 w0 = *(const float4*)(Wo + lane * 4);
    float4 w1 = *(const float4*)(Wo + DD + lane * 4);
    float p0 = h.x * w0.x + h.y * w0.y + h.z * w0.z + h.w * w0.w;
    float p1 = h.x * w1.x + h.y * w1.y + h.z * w1.z + h.w * w1.w;
    for (int off = 16; off; off >>= 1) {
        p0 += __shfl_xor_sync(0xffffffffu, p0, off);
        p1 += __shfl_xor_sync(0xffffffffu, p1, off);
    }
    if (lane == 0) {
        out2[w * 2 + 0] = p0 + bo[0];
        out2[w * 2 + 1] = p1 + bo[1];
    }
}

extern "C" void kernel_launch(void* const* d_in, const int* in_sizes, int n_in,
                              void* d_out, int out_size) {
    const float* x   = (const float*)d_in[0];
    const int*   eiw = (const int*)d_in[1];
    const float* Wl1 = (const float*)d_in[2];
    const float* Wr1 = (const float*)d_in[3];
    const float* b1  = (const float*)d_in[4];
    const float* Wl2 = (const float*)d_in[5];
    const float* Wr2 = (const float*)d_in[6];
    const float* b2  = (const float*)d_in[7];
    const float* Wl3 = (const float*)d_in[8];
    const float* Wr3 = (const float*)d_in[9];
    const float* b3  = (const float*)d_in[10];
    const float* Wo  = (const float*)d_in[11];
    const float* bo  = (const float*)d_in[12];

    float* out  = (float*)d_out;
    float* out2 = out;              // [N, 2]
    float* h3   = out + NN * 2;     // [N, 128]

    // CSR build (edges identical across layers)
    k_detect<<<1, 32>>>(eiw);
    k_zero_cnt<<<(NN + 255) / 256, 256>>>();
    k_count<<<(EE + 255) / 256, 256>>>(eiw);
    k_scan1<<<NB, 1024>>>();
    k_scan2<<<1, 32>>>();
    k_scan3<<<NB, 1024>>>();
    k_fill<<<(EE + 255) / 256, 256>>>(eiw);

    int warp_blocks = (NN + 7) / 8;

    // layer 1: x -> g_h1 (relu)
    k_aggregate<<<warp_blocks, 256>>>(x, 0);
    k_gemm<<<GB, 256>>>(x, 0, Wl1, Wr1, b1, nullptr, 1, 1);

    // layer 2: g_h1 -> g_h2 (relu)
    k_aggregate<<<warp_blocks, 256>>>(nullptr, 1);
    k_gemm<<<GB, 256>>>(nullptr, 1, Wl2, Wr2, b2, nullptr, 2, 1);

    // layer 3: g_h2 -> h3 (no relu), straight into d_out
    k_aggregate<<<warp_blocks, 256>>>(nullptr, 2);
    k_gemm<<<GB, 256>>>(nullptr, 2, Wl3, Wr3, b3, h3, 0, 0);

    // decoder
    k_decoder<<<warp_blocks, 256>>>(h3, Wo, bo, out2);
}